// round 5
// baseline (speedup 1.0000x reference)
#include <cuda_runtime.h>
#include <cstdint>
#include <math.h>

typedef unsigned long long ull;

// Problem constants
#define B_    32
#define L_    2048
#define I_    256
#define H_    512
#define HX    768      // H + I
#define N3    1536     // 3*H (z | r | w)
#define NCG   32       // column groups (CTAs per batch group)
#define NBG   8        // batch groups
#define BPG   4        // batches per group
#define CPG   16       // gate columns per CTA per gate
#define NTHR  128

// ---------------- device scratch ----------------
__device__ float g_X[(size_t)L_ * B_ * N3];   // precomputed x-contributions
__device__ float g_rh[B_ * H_];               // r*h exchange
__device__ unsigned g_cnt[NBG * 32];          // per-group barrier counters (padded lines)
__device__ unsigned g_genv[NBG * 32];         // per-group barrier generations

// ---------------- smem layout (float offsets) ----------------
#define WR_F 0                   // 16 x 512
#define WZ_F (16 * 512)
#define WW_F (32 * 512)
#define HB_F (48 * 512)          // 4 x 512 (h, later reused for r*h)
#define SM_FLOATS (HB_F + 4 * 512)
#define SMEM_BYTES (SM_FLOATS * 4)   // 106,496 B -> 2 CTAs/SM

// ---------------- asm helpers ----------------
__device__ __forceinline__ uint32_t smem_u32(const void* p) {
    uint32_t a;
    asm("{ .reg .u64 t; cvta.to.shared.u64 t, %1; cvt.u32.u64 %0, t; }" : "=r"(a) : "l"(p));
    return a;
}
__device__ __forceinline__ ull lds64(uint32_t a) {
    ull v;
    asm volatile("ld.shared.b64 %0, [%1];" : "=l"(v) : "r"(a));
    return v;
}
__device__ __forceinline__ void fma2(ull& acc, ull a, ull b) {
    asm volatile("fma.rn.f32x2 %0, %1, %2, %0;" : "+l"(acc) : "l"(a), "l"(b));
}
__device__ __forceinline__ float sum2(ull v) {
    float lo, hi;
    asm("mov.b64 {%0, %1}, %2;" : "=f"(lo), "=f"(hi) : "l"(v));
    return lo + hi;
}

// ---------------- barrier (arrive / wait split, tid0 poll) ----------------
__device__ __forceinline__ void bar_arrive(int bg, unsigned target) {
    __threadfence();
    unsigned* cnt = &g_cnt[bg * 32];
    unsigned* gen = &g_genv[bg * 32];
    if (atomicAdd(cnt, 1u) == (unsigned)(NCG - 1)) {
        *cnt = 0u;
        __threadfence();
        atomicExch(gen, target);
    }
}
__device__ __forceinline__ void bar_wait_all(int bg, unsigned target, int tid) {
    if (tid == 0) {
        unsigned* gen = &g_genv[bg * 32];
        unsigned v;
        do {
            asm volatile("ld.acquire.gpu.u32 %0, [%1];" : "=r"(v) : "l"(gen) : "memory");
        } while ((int)(v - target) < 0);
    }
    __syncthreads();
}

// ---------------- warp reduction: 16 chains over 32 lanes ----------------
// After return: thread pair (2l, 2l+1) holds chain o = (lane>>1)&15 in a[0].
__device__ __forceinline__ void reduce16(float a[16], int lane) {
#pragma unroll
    for (int o = 0; o < 8; o++) {
        bool hi = (lane & 16);
        float send = hi ? a[o] : a[o + 8];
        float keep = hi ? a[o + 8] : a[o];
        a[o] = keep + __shfl_xor_sync(0xffffffffu, send, 16);
    }
#pragma unroll
    for (int o = 0; o < 4; o++) {
        bool hi = (lane & 8);
        float send = hi ? a[o] : a[o + 4];
        float keep = hi ? a[o + 4] : a[o];
        a[o] = keep + __shfl_xor_sync(0xffffffffu, send, 8);
    }
#pragma unroll
    for (int o = 0; o < 2; o++) {
        bool hi = (lane & 4);
        float send = hi ? a[o] : a[o + 2];
        float keep = hi ? a[o + 2] : a[o];
        a[o] = keep + __shfl_xor_sync(0xffffffffu, send, 4);
    }
    {
        bool hi = (lane & 2);
        float send = hi ? a[0] : a[1];
        float keep = hi ? a[1] : a[0];
        a[0] = keep + __shfl_xor_sync(0xffffffffu, send, 2);
    }
    a[0] += __shfl_xor_sync(0xffffffffu, a[0], 1);
}

// ---------------- precompute GEMM: g_X = x . W[:,512:768]^T ----------------
__global__ void __launch_bounds__(256) precompute_x_kernel(
    const float* __restrict__ x,
    const float* __restrict__ Wz,
    const float* __restrict__ Wr,
    const float* __restrict__ Ww)
{
    __shared__ float As[16][132];
    __shared__ float Bs[16][132];

    const int m0 = blockIdx.y * 128;
    const int n0 = blockIdx.x * 128;
    const int tid = threadIdx.x;
    const int ty = tid >> 4;
    const int tx = tid & 15;

    float acc[8][8];
#pragma unroll
    for (int i = 0; i < 8; i++)
#pragma unroll
        for (int j = 0; j < 8; j++) acc[i][j] = 0.f;

    for (int k0 = 0; k0 < 256; k0 += 16) {
#pragma unroll
        for (int q = tid; q < 512; q += 256) {
            int r  = q >> 2;
            int kq = (q & 3) << 2;
            float4 v = *(const float4*)(x + (size_t)(m0 + r) * 256 + k0 + kq);
            As[kq + 0][r] = v.x; As[kq + 1][r] = v.y;
            As[kq + 2][r] = v.z; As[kq + 3][r] = v.w;
        }
#pragma unroll
        for (int q = tid; q < 512; q += 256) {
            int r  = q >> 2;
            int kq = (q & 3) << 2;
            int n  = n0 + r;
            const float* wrow;
            if (n < 512)        wrow = Wz + (size_t)n * HX;
            else if (n < 1024)  wrow = Wr + (size_t)(n - 512) * HX;
            else                wrow = Ww + (size_t)(n - 1024) * HX;
            float4 v = *(const float4*)(wrow + 512 + k0 + kq);
            Bs[kq + 0][r] = v.x; Bs[kq + 1][r] = v.y;
            Bs[kq + 2][r] = v.z; Bs[kq + 3][r] = v.w;
        }
        __syncthreads();
#pragma unroll
        for (int kk = 0; kk < 16; kk++) {
            float a[8], b[8];
#pragma unroll
            for (int i = 0; i < 8; i++) a[i] = As[kk][ty * 8 + i];
#pragma unroll
            for (int j = 0; j < 8; j++) b[j] = Bs[kk][tx * 8 + j];
#pragma unroll
            for (int i = 0; i < 8; i++)
#pragma unroll
                for (int j = 0; j < 8; j++) acc[i][j] += a[i] * b[j];
        }
        __syncthreads();
    }

#pragma unroll
    for (int i = 0; i < 8; i++) {
        int m = m0 + ty * 8 + i;
        int t = m & 2047;
        int b = m >> 11;
        size_t base = ((size_t)t * B_ + b) * N3 + n0 + tx * 8;
        *(float4*)&g_X[base + 0] = make_float4(acc[i][0], acc[i][1], acc[i][2], acc[i][3]);
        *(float4*)&g_X[base + 4] = make_float4(acc[i][4], acc[i][5], acc[i][6], acc[i][7]);
    }
}

// ---------------- persistent recurrent kernel (256 CTAs, 2/SM) ----------------
__global__ void __launch_bounds__(NTHR, 2) gru_persistent_kernel(
    const float* __restrict__ h0,
    const float* __restrict__ Wz,
    const float* __restrict__ Wr,
    const float* __restrict__ Ww,
    float* __restrict__ out)
{
    extern __shared__ float sm[];
    const uint32_t sb = smem_u32(sm);
    const int tid  = threadIdx.x;
    const int wg   = tid >> 5;           // 0..3
    const int lane = tid & 31;
    const int cta  = blockIdx.x;
    const int bg   = cta & (NBG - 1);    // interleaved: adjacent bids -> different groups
    const int cg   = cta >> 3;           // 0..31
    const int b0   = bg * BPG;
    const int c0   = cg * CPG;

    // ---- cache weight h-parts: 3 x [16 rows x 512] ----
    for (int q = tid; q < 16 * 128; q += NTHR) {
        int row = q >> 7, f4 = q & 127;
        ((float4*)(sm + WR_F))[row * 128 + f4] = *(const float4*)(Wr + (size_t)(c0 + row) * HX + f4 * 4);
        ((float4*)(sm + WZ_F))[row * 128 + f4] = *(const float4*)(Wz + (size_t)(c0 + row) * HX + f4 * 4);
        ((float4*)(sm + WW_F))[row * 128 + f4] = *(const float4*)(Ww + (size_t)(c0 + row) * HX + f4 * 4);
    }
    __syncthreads();

    unsigned gen0;
    asm volatile("ld.acquire.gpu.u32 %0, [%1];" : "=r"(gen0) : "l"(&g_genv[bg * 32]) : "memory");

    // output mapping: even lanes own output o = (lane>>1)&15 = c*4+b
    const int o   = (lane >> 1) & 15;
    const int oc  = o >> 2;              // col within warp's 4
    const int ob  = o & 3;               // batch within group
    const int colg = c0 + wg * 4 + oc;   // global gate column (0..511)
    const bool wr = !(lane & 1);

    // prefetch x-contributions for t=0
    size_t xbase = ((size_t)0 * B_ + b0 + ob) * N3;
    float xz = __ldg(&g_X[xbase + colg]);
    float xr = __ldg(&g_X[xbase + 512 + colg]);
    float xw = __ldg(&g_X[xbase + 1024 + colg]);

    for (int t = 0; t < L_; t++) {
        const float* hsrc = (t == 0) ? h0 : (out + (size_t)(t - 1) * B_ * H_);

        // ---- stage h(t) for our 4 batches ----
        for (int q = tid; q < 512; q += NTHR) {
            int b = q >> 7, f4 = q & 127;
            float4 v = __ldcg(((const float4*)(hsrc + (size_t)(b0 + b) * H_)) + f4);
            *(float4*)(sm + HB_F + b * 512 + f4 * 4) = v;
        }
        __syncthreads();

        // ---- load h slice into registers (reused by r and z gates) ----
        ull hb[4][8];
#pragma unroll
        for (int b = 0; b < 4; b++)
#pragma unroll
            for (int i = 0; i < 8; i++)
                hb[b][i] = lds64(sb + (HB_F + b * 512) * 4 + (i * 32 + lane) * 8);
        float hval = sm[HB_F + ob * 512 + colg];   // h element this thread owns

        // ================= r gate =================
        {
            ull acc[4][4];
#pragma unroll
            for (int c = 0; c < 4; c++)
#pragma unroll
                for (int b = 0; b < 4; b++) acc[c][b] = 0ull;

            const uint32_t wb = sb + (WR_F + (wg * 4) * 512) * 4;
#pragma unroll
            for (int i = 0; i < 8; i++) {
                uint32_t off = (uint32_t)(i * 32 + lane) * 8u;
#pragma unroll
                for (int c = 0; c < 4; c++) {
                    ull wv = lds64(wb + c * 2048 + off);
                    fma2(acc[c][0], hb[0][i], wv);
                    fma2(acc[c][1], hb[1][i], wv);
                    fma2(acc[c][2], hb[2][i], wv);
                    fma2(acc[c][3], hb[3][i], wv);
                }
            }
            float a[16];
#pragma unroll
            for (int c = 0; c < 4; c++)
#pragma unroll
                for (int b = 0; b < 4; b++) a[c * 4 + b] = sum2(acc[c][b]);
            reduce16(a, lane);

            if (wr) {
                float r = 1.f / (1.f + __expf(-(a[0] + xr)));
                __stcg(&g_rh[(size_t)(b0 + ob) * H_ + colg], r * hval);
            }
        }
        __syncthreads();
        if (tid == 0) bar_arrive(bg, gen0 + (unsigned)(2 * t + 1));

        // ================= z gate (overlaps barrier A propagation) =================
        float zv = 0.f;
        {
            ull acc[4][4];
#pragma unroll
            for (int c = 0; c < 4; c++)
#pragma unroll
                for (int b = 0; b < 4; b++) acc[c][b] = 0ull;

            const uint32_t wb = sb + (WZ_F + (wg * 4) * 512) * 4;
#pragma unroll
            for (int i = 0; i < 8; i++) {
                uint32_t off = (uint32_t)(i * 32 + lane) * 8u;
#pragma unroll
                for (int c = 0; c < 4; c++) {
                    ull wv = lds64(wb + c * 2048 + off);
                    fma2(acc[c][0], hb[0][i], wv);
                    fma2(acc[c][1], hb[1][i], wv);
                    fma2(acc[c][2], hb[2][i], wv);
                    fma2(acc[c][3], hb[3][i], wv);
                }
            }
            float a[16];
#pragma unroll
            for (int c = 0; c < 4; c++)
#pragma unroll
                for (int b = 0; b < 4; b++) a[c * 4 + b] = sum2(acc[c][b]);
            reduce16(a, lane);
            zv = 1.f / (1.f + __expf(-(a[0] + xz)));
        }

        // ---- wait for all r*h in group, then stage it (reuse h buffer) ----
        bar_wait_all(bg, gen0 + (unsigned)(2 * t + 1), tid);
        for (int q = tid; q < 512; q += NTHR) {
            int b = q >> 7, f4 = q & 127;
            float4 v = __ldcg(((const float4*)(g_rh + (size_t)(b0 + b) * H_)) + f4);
            *(float4*)(sm + HB_F + b * 512 + f4 * 4) = v;
        }
        __syncthreads();

        // ================= w gate (candidate) + blend =================
        {
            ull rb[4][8];
#pragma unroll
            for (int b = 0; b < 4; b++)
#pragma unroll
                for (int i = 0; i < 8; i++)
                    rb[b][i] = lds64(sb + (HB_F + b * 512) * 4 + (i * 32 + lane) * 8);

            ull acc[4][4];
#pragma unroll
            for (int c = 0; c < 4; c++)
#pragma unroll
                for (int b = 0; b < 4; b++) acc[c][b] = 0ull;

            const uint32_t wb = sb + (WW_F + (wg * 4) * 512) * 4;
#pragma unroll
            for (int i = 0; i < 8; i++) {
                uint32_t off = (uint32_t)(i * 32 + lane) * 8u;
#pragma unroll
                for (int c = 0; c < 4; c++) {
                    ull wv = lds64(wb + c * 2048 + off);
                    fma2(acc[c][0], rb[0][i], wv);
                    fma2(acc[c][1], rb[1][i], wv);
                    fma2(acc[c][2], rb[2][i], wv);
                    fma2(acc[c][3], rb[3][i], wv);
                }
            }
            float a[16];
#pragma unroll
            for (int c = 0; c < 4; c++)
#pragma unroll
                for (int b = 0; b < 4; b++) a[c * 4 + b] = sum2(acc[c][b]);
            reduce16(a, lane);

            if (wr) {
                float hh = tanhf(a[0] + xw);
                float hn = hval + zv * (hh - hval);
                __stcg(&out[((size_t)t * B_ + b0 + ob) * H_ + colg], hn);
            }
        }

        // ---- prefetch x-contributions for t+1 (independent of barrier) ----
        {
            int tn = (t + 1 < L_) ? (t + 1) : t;
            xbase = ((size_t)tn * B_ + b0 + ob) * N3;
            xz = __ldg(&g_X[xbase + colg]);
            xr = __ldg(&g_X[xbase + 512 + colg]);
            xw = __ldg(&g_X[xbase + 1024 + colg]);
        }

        __syncthreads();
        if (tid == 0) bar_arrive(bg, gen0 + (unsigned)(2 * t + 2));
        bar_wait_all(bg, gen0 + (unsigned)(2 * t + 2), tid);
    }
}

// ---------------- launch ----------------
extern "C" void kernel_launch(void* const* d_in, const int* in_sizes, int n_in,
                              void* d_out, int out_size)
{
    const float* x  = (const float*)d_in[0];   // [32, 2048, 256]
    const float* h0 = (const float*)d_in[1];   // [32, 512]
    const float* Wz = (const float*)d_in[2];   // [512, 768]
    const float* Wr = (const float*)d_in[3];   // [512, 768]
    const float* Ww = (const float*)d_in[4];   // [512, 768]
    float* out = (float*)d_out;                // [2048, 32, 512]

    cudaFuncSetAttribute(gru_persistent_kernel,
                         cudaFuncAttributeMaxDynamicSharedMemorySize, SMEM_BYTES);

    dim3 pgrid(N3 / 128, (B_ * L_) / 128);     // (12, 512)
    precompute_x_kernel<<<pgrid, 256>>>(x, Wz, Wr, Ww);

    gru_persistent_kernel<<<NCG * NBG, NTHR, SMEM_BYTES>>>(h0, Wz, Wr, Ww, out);
}